// round 6
// baseline (speedup 1.0000x reference)
#include <cuda_runtime.h>
#include <math.h>

#define N_IN 12288
#define H0 256
#define H1 32
#define H2 32
#define NB 8192
#define ROWS_P1 4          // rows per phase-1 CTA
#define SEG_CAP 64         // per-warp-segment index capacity (mean nnz/seg ~3.8)
#define FULL 0xffffffffu

// Transposed ft weights: column j = 256 contiguous floats (12.6 MB, L2-resident).
__device__ float g_ftT[N_IN * H0];
// Phase-1 output: clamped, side-swapped accumulators [NB][512] (16 MB).
__device__ float g_acc[NB * 2 * H0];
// 0 = 32-bit words (int32 or fp32; !=0 test covers both), 1 = packed bytes.
__device__ int g_side_mode;

__global__ void detect_side_mode(const unsigned int* __restrict__ w) {
    int lane = threadIdx.x;
    bool bad = false;
#pragma unroll
    for (int i = 0; i < 8; i++) {
        unsigned int v = w[i * 32 + lane];   // 1 KB sample, safe for all encodings
        bad |= (v != 0u && v != 1u && v != 0x3f800000u);
    }
    unsigned m = __ballot_sync(FULL, bad);
    if (lane == 0) g_side_mode = (m != 0u) ? 1 : 0;
}

__global__ void transpose_ft(const float* __restrict__ ftw) {
    __shared__ float tile[32][33];
    int j0 = blockIdx.x * 32, h0 = blockIdx.y * 32;
    int tx = threadIdx.x, ty = threadIdx.y;
#pragma unroll
    for (int r = 0; r < 32; r += 8)
        tile[ty + r][tx] = ftw[(size_t)(h0 + ty + r) * N_IN + j0 + tx];
    __syncthreads();
#pragma unroll
    for (int r = 0; r < 32; r += 8)
        g_ftT[(size_t)(j0 + ty + r) * H0 + h0 + tx] = tile[tx][ty + r];
}

__device__ __forceinline__ float clamp01(float x) { return fminf(fmaxf(x, 0.f), 1.f); }

// ============================================================================
// Phase 1: sparse feature transform. 256 threads x 12 uint4 = 3072 uint4 =
// FULL 12288-float row (R5 bug: warp-only coverage). Each warp ballot/popc-
// compacts its 1536-feature slice into a private smem segment -> no LMEM,
// no cross-warp prefix sum. Gather walks the 8 segments in fixed order.
// ============================================================================
__global__ __launch_bounds__(256) void phase1(
    const float* __restrict__ wf, const float* __restrict__ bf,
    const void* __restrict__ side, const float* __restrict__ ftb)
{
    __shared__ unsigned short wl[8][SEG_CAP];
    __shared__ unsigned short bl[8][SEG_CAP];
    __shared__ int wcnt[8], bcnt[8];

    const int t = threadIdx.x, lane = t & 31, wid = t >> 5;
    const unsigned lt = (1u << lane) - 1u;
    const float ftbt = ftb[t];
    const int mode = g_side_mode;

    for (int r = 0; r < ROWS_P1; r++) {
        const int row = blockIdx.x * ROWS_P1 + r;

        // ---- scan both sides: warp w covers uint4 positions i*256 + w*32+lane ----
#pragma unroll
        for (int sde = 0; sde < 2; sde++) {
            const uint4* rowp = (const uint4*)((sde ? bf : wf) + (size_t)row * N_IN);
            unsigned short* seg = sde ? bl[wid] : wl[wid];
            int n = 0;
#pragma unroll
            for (int i = 0; i < 12; i++) {
                int p = i * 256 + wid * 32 + lane;       // coalesced 128B/warp
                uint4 v = rowp[p];
                bool f0 = v.x != 0u, f1 = v.y != 0u, f2 = v.z != 0u, f3 = v.w != 0u;
                unsigned b0 = __ballot_sync(FULL, f0);
                unsigned b1 = __ballot_sync(FULL, f1);
                unsigned b2 = __ballot_sync(FULL, f2);
                unsigned b3 = __ballot_sync(FULL, f3);
                if (b0 | b1 | b2 | b3) {   // ~96% of chunks all-zero warp-wide
                    int ib = p * 4;
                    int c0 = __popc(b0), c01 = c0 + __popc(b1), c012 = c01 + __popc(b2);
                    if (f0) { int q = n + __popc(b0 & lt);        if (q < SEG_CAP) seg[q] = (unsigned short)ib; }
                    if (f1) { int q = n + c0 + __popc(b1 & lt);   if (q < SEG_CAP) seg[q] = (unsigned short)(ib + 1); }
                    if (f2) { int q = n + c01 + __popc(b2 & lt);  if (q < SEG_CAP) seg[q] = (unsigned short)(ib + 2); }
                    if (f3) { int q = n + c012 + __popc(b3 & lt); if (q < SEG_CAP) seg[q] = (unsigned short)(ib + 3); }
                    n += c012 + __popc(b3);
                }
            }
            if (lane == 0) (sde ? bcnt : wcnt)[wid] = min(n, SEG_CAP);
        }
        __syncthreads();

        // ---- gather: thread t owns hidden unit t; fixed segment order ----
        float ws0 = 0.f, ws1 = 0.f, bs0 = 0.f, bs1 = 0.f;
#pragma unroll
        for (int s = 0; s < 8; s++) {
            {
                int n = wcnt[s];
                const unsigned short* seg = wl[s];
                int k = 0;
                for (; k + 2 <= n; k += 2) {
                    ws0 += g_ftT[(int)seg[k]     * H0 + t];
                    ws1 += g_ftT[(int)seg[k + 1] * H0 + t];
                }
                if (k < n) ws0 += g_ftT[(int)seg[k] * H0 + t];
            }
            {
                int n = bcnt[s];
                const unsigned short* seg = bl[s];
                int k = 0;
                for (; k + 2 <= n; k += 2) {
                    bs0 += g_ftT[(int)seg[k]     * H0 + t];
                    bs1 += g_ftT[(int)seg[k + 1] * H0 + t];
                }
                if (k < n) bs0 += g_ftT[(int)seg[k] * H0 + t];
            }
        }
        float aw = ftbt + (ws0 + ws1);
        float ab = ftbt + (bs0 + bs1);

        bool sd = mode ? (((const unsigned char*)side)[row] != 0)
                       : (((const unsigned int*)side)[row] != 0u);
        float* o = g_acc + (size_t)row * 2 * H0;
        o[t]      = clamp01(sd ? aw : ab);
        o[H0 + t] = clamp01(sd ? ab : aw);
        __syncthreads();   // lists reusable next row
    }
}

// ============================================================================
// Phase 2: warp-per-row MLP. l1w staged once in smem; after staging each warp
// is autonomous: shfl-butterfly reductions, l2 via shfl broadcast, fused
// l3 + sigmoid.
// ============================================================================
struct Smem2 {
    float l1w[H1 * 2 * H0];          // 64 KB
    float l2w[H2 * (H1 + 1)];        // padded stride 33
    float l3w[H2];
    float l1b[H1];
    float l2b[H2];
    float l3b;
};

__global__ __launch_bounds__(256) void phase2(
    const float* __restrict__ l1w, const float* __restrict__ l1b,
    const float* __restrict__ l2w, const float* __restrict__ l2b,
    const float* __restrict__ l3w, const float* __restrict__ l3b,
    float* __restrict__ out)
{
    extern __shared__ unsigned char raw[];
    Smem2* S = (Smem2*)raw;
    int t = threadIdx.x, lane = t & 31, wid = t >> 5;
    {
        const float4* src = (const float4*)l1w;
        float4* dst = (float4*)S->l1w;
        for (int i = t; i < H1 * 2 * H0 / 4; i += 256) dst[i] = src[i];
        for (int i = t; i < H2 * H1; i += 256)
            S->l2w[(i >> 5) * (H1 + 1) + (i & 31)] = l2w[i];
        if (t < H2) S->l3w[t] = l3w[t];
        if (t < H1) S->l1b[t] = l1b[t];
        if (t < H2) S->l2b[t] = l2b[t];
        if (t == 0) S->l3b = l3b[0];
    }
    __syncthreads();

    int row = blockIdx.x * 8 + wid;
    const float4* xr = ((const float4*)g_acc) + (size_t)row * 128;
    float4 x0 = xr[lane], x1 = xr[32 + lane], x2 = xr[64 + lane], x3 = xr[96 + lane];

    const float4* W = (const float4*)S->l1w;
    float v1 = 0.f;
#pragma unroll
    for (int o = 0; o < H1; o++) {
        const float4* wr = W + o * 128;
        float4 w0 = wr[lane], w1 = wr[32 + lane], w2 = wr[64 + lane], w3 = wr[96 + lane];
        float s = ((x0.x * w0.x + x0.y * w0.y) + (x0.z * w0.z + x0.w * w0.w))
                + ((x1.x * w1.x + x1.y * w1.y) + (x1.z * w1.z + x1.w * w1.w))
                + ((x2.x * w2.x + x2.y * w2.y) + (x2.z * w2.z + x2.w * w2.w))
                + ((x3.x * w3.x + x3.y * w3.y) + (x3.z * w3.z + x3.w * w3.w));
#pragma unroll
        for (int off = 16; off; off >>= 1) s += __shfl_xor_sync(FULL, s, off);
        if (lane == o) v1 = clamp01(s + S->l1b[o]);
    }
    float s2 = 0.f;
#pragma unroll
    for (int k = 0; k < H1; k++)
        s2 += S->l2w[lane * (H1 + 1) + k] * __shfl_sync(FULL, v1, k);
    float v = clamp01(s2 + S->l2b[lane]) * S->l3w[lane];
#pragma unroll
    for (int off = 16; off; off >>= 1) v += __shfl_xor_sync(FULL, v, off);
    if (lane == 0)
        out[row] = 1.f / (1.f + expf(-(v + S->l3b) * 1.5f));  // 300/200 = 1.5
}

extern "C" void kernel_launch(void* const* d_in, const int* in_sizes, int n_in,
                              void* d_out, int out_size) {
    const float* wf  = (const float*)d_in[0];
    const float* bf  = (const float*)d_in[1];
    const void*  side = d_in[2];
    const float* ftw = (const float*)d_in[3];
    const float* ftb = (const float*)d_in[4];
    const float* l1w = (const float*)d_in[5];
    const float* l1b = (const float*)d_in[6];
    const float* l2w = (const float*)d_in[7];
    const float* l2b = (const float*)d_in[8];
    const float* l3w = (const float*)d_in[9];
    const float* l3b = (const float*)d_in[10];
    float* out = (float*)d_out;

    cudaFuncSetAttribute(phase2, cudaFuncAttributeMaxDynamicSharedMemorySize,
                         (int)sizeof(Smem2));

    detect_side_mode<<<1, 32>>>((const unsigned int*)side);
    transpose_ft<<<dim3(N_IN / 32, H0 / 32), dim3(32, 8)>>>(ftw);
    phase1<<<NB / ROWS_P1, 256>>>(wf, bf, side, ftb);
    phase2<<<NB / 8, 256, sizeof(Smem2)>>>(l1w, l1b, l2w, l2b, l3w, l3b, out);
}

// round 7
// speedup vs baseline: 2.1877x; 2.1877x over previous
#include <cuda_runtime.h>
#include <math.h>

#define N_IN 12288
#define H0 256
#define H1 32
#define H2 32
#define NB 8192
#define SEG_CAP 32        // per-warp-slice capacity (Binomial(1536,.0025): mean 3.8, z>14 safe)
#define FULL 0xffffffffu

// Transposed ft weights: column j = 256 contiguous floats (12.6 MB, L2-resident).
__device__ float g_ftT[N_IN * H0];
// Sparse index lists: [row-side R][warp-slice 8][SEG_CAP] u16 (8 MB), + packed u8 counts.
__device__ unsigned short g_lists[NB * 2 * 8 * SEG_CAP];
__device__ unsigned char g_cnt[NB * 2 * 8];
// Raw (unswapped, unclamped, no-bias) accumulators [R][256] (16 MB).
__device__ float g_accraw[NB * 2 * H0];
// 0 = 32-bit words (int32/fp32; !=0 covers both), 1 = packed bytes.
__device__ int g_side_mode;

__global__ void detect_side_mode(const unsigned int* __restrict__ w) {
    int lane = threadIdx.x;
    bool bad = false;
#pragma unroll
    for (int i = 0; i < 8; i++) {
        unsigned int v = w[i * 32 + lane];
        bad |= (v != 0u && v != 1u && v != 0x3f800000u);
    }
    unsigned m = __ballot_sync(FULL, bad);
    if (lane == 0) g_side_mode = (m != 0u) ? 1 : 0;
}

__global__ void transpose_ft(const float* __restrict__ ftw) {
    __shared__ float tile[32][33];
    int j0 = blockIdx.x * 32, h0 = blockIdx.y * 32;
    int tx = threadIdx.x, ty = threadIdx.y;
#pragma unroll
    for (int r = 0; r < 32; r += 8)
        tile[ty + r][tx] = ftw[(size_t)(h0 + ty + r) * N_IN + j0 + tx];
    __syncthreads();
#pragma unroll
    for (int r = 0; r < 32; r += 8)
        g_ftT[(size_t)(j0 + ty + r) * H0 + h0 + tx] = tile[tx][ty + r];
}

__device__ __forceinline__ float clamp01(float x) { return fminf(fmaxf(x, 0.f), 1.f); }
__device__ __forceinline__ float4 clamp4(float4 a) {
    return make_float4(clamp01(a.x), clamp01(a.y), clamp01(a.z), clamp01(a.w));
}
__device__ __forceinline__ void add4(float4& a, float4 u) {
    a.x += u.x; a.y += u.y; a.z += u.z; a.w += u.w;
}

// ============================================================================
// 1) SCAN: one CTA per row-side. Pure coalesced DRAM stream; ballot-compact
// indices straight to gmem. No smem, no block barriers.
// ============================================================================
__global__ __launch_bounds__(256) void scan_kernel(
    const float* __restrict__ wf, const float* __restrict__ bf)
{
    const int R = blockIdx.x;                       // row-side: row=R>>1, side=R&1
    const float* base = (R & 1) ? bf : wf;
    const uint4* rowp = (const uint4*)(base + (size_t)(R >> 1) * N_IN);
    const int t = threadIdx.x, lane = t & 31, wid = t >> 5;
    const unsigned lt = (1u << lane) - 1u;
    unsigned short* seg = g_lists + (size_t)R * 8 * SEG_CAP + wid * SEG_CAP;

    int n = 0;
#pragma unroll
    for (int i = 0; i < 12; i++) {
        uint4 v = rowp[i * 256 + t];                 // coalesced 128B/warp
        bool f0 = v.x != 0u, f1 = v.y != 0u, f2 = v.z != 0u, f3 = v.w != 0u;
        unsigned b0 = __ballot_sync(FULL, f0);
        unsigned b1 = __ballot_sync(FULL, f1);
        unsigned b2 = __ballot_sync(FULL, f2);
        unsigned b3 = __ballot_sync(FULL, f3);
        if (b0 | b1 | b2 | b3) {                     // ~96% all-zero warp-wide
            int ib = (i * 256 + t) * 4;
            int c0 = __popc(b0), c01 = c0 + __popc(b1), c012 = c01 + __popc(b2);
            if (f0) { int q = n + __popc(b0 & lt);        if (q < SEG_CAP) seg[q] = (unsigned short)ib; }
            if (f1) { int q = n + c0 + __popc(b1 & lt);   if (q < SEG_CAP) seg[q] = (unsigned short)(ib + 1); }
            if (f2) { int q = n + c01 + __popc(b2 & lt);  if (q < SEG_CAP) seg[q] = (unsigned short)(ib + 2); }
            if (f3) { int q = n + c012 + __popc(b3 & lt); if (q < SEG_CAP) seg[q] = (unsigned short)(ib + 3); }
            n += c012 + __popc(b3);
        }
    }
    if (lane == 0) g_cnt[R * 8 + wid] = (unsigned char)min(n, SEG_CAP);
}

// ============================================================================
// 2) GATHER: one warp per row-side (16384 warps, no block barriers). Runs
// after streaming ends -> ft table undisturbed in L2 -> pure L2 hits.
// Per index: 2x LDG.128/lane = full 1KB column per warp. 4 alternating
// accumulators for ILP; fixed order -> deterministic.
// ============================================================================
__global__ __launch_bounds__(256) void gather_kernel()
{
    const int R = blockIdx.x * 8 + (threadIdx.x >> 5);
    const int lane = threadIdx.x & 31;
    const uint2 c2 = *(const uint2*)(g_cnt + (size_t)R * 8);
    const unsigned short* lists = g_lists + (size_t)R * 8 * SEG_CAP;
    const float4* tab = (const float4*)g_ftT;

    float4 a0 = make_float4(0, 0, 0, 0), a1 = a0, a2 = a0, a3 = a0;
#pragma unroll
    for (int s = 0; s < 8; s++) {
        int n = ((s < 4 ? c2.x >> (8 * s) : c2.y >> (8 * (s - 4))) & 0xff);
        const unsigned short* seg = lists + s * SEG_CAP;
        int k = 0;
        for (; k + 2 <= n; k += 2) {
            int i0 = seg[k], i1 = seg[k + 1];        // broadcast u16 loads
            const float4* p0 = tab + i0 * 64 + lane * 2;
            const float4* p1 = tab + i1 * 64 + lane * 2;
            float4 u0 = p0[0], u1 = p0[1], u2 = p1[0], u3 = p1[1];
            add4(a0, u0); add4(a1, u1); add4(a2, u2); add4(a3, u3);
        }
        if (k < n) {
            int i0 = seg[k];
            const float4* p0 = tab + i0 * 64 + lane * 2;
            float4 u0 = p0[0], u1 = p0[1];
            add4(a0, u0); add4(a1, u1);
        }
    }
    float4 r0, r1;                                    // fixed combine order
    r0.x = a0.x + a2.x; r0.y = a0.y + a2.y; r0.z = a0.z + a2.z; r0.w = a0.w + a2.w;
    r1.x = a1.x + a3.x; r1.y = a1.y + a3.y; r1.z = a1.z + a3.z; r1.w = a1.w + a3.w;
    float4* o = ((float4*)g_accraw) + (size_t)R * 64 + lane * 2;
    o[0] = r0; o[1] = r1;                             // lane owns units lane*8..+7
}

// ============================================================================
// 3) MLP: 16 rows per CTA, 2 rows per warp. Lane o owns output o -> NO shfl
// reduction in l1/l2. w4 smem layout [o][k4] stride 129 float4: lanes
// 8k..8k+7 cover all 32 banks per 128b-phase -> conflict-free. ftb add,
// clamp, side-swap fused into x staging.
// ============================================================================
struct SmemM {
    float4 w4[32 * 129];     // l1w
    float4 x4[16 * 128];     // 16 rows x 512 inputs
    float o1[16 * 33];
    float l2w[32 * 33];      // (lane+k)%32 conflict-free
    float l3w[32], l1b[32], l2b[32];
    float l3b;
};

__global__ __launch_bounds__(256) void mlp_kernel(
    const void* __restrict__ side, const float* __restrict__ ftb,
    const float* __restrict__ l1w, const float* __restrict__ l1b,
    const float* __restrict__ l2w, const float* __restrict__ l2b,
    const float* __restrict__ l3w, const float* __restrict__ l3b,
    float* __restrict__ out)
{
    extern __shared__ unsigned char raw[];
    SmemM* S = (SmemM*)raw;
    const int t = threadIdx.x, lane = t & 31, wid = t >> 5;
    const int row0 = blockIdx.x * 16;
    const int mode = g_side_mode;

    for (int i = t; i < 32 * 128; i += 256) {
        int o = i >> 7, k4 = i & 127;
        S->w4[o * 129 + k4] = ((const float4*)l1w)[i];
    }
    for (int i = t; i < 32 * 32; i += 256)
        S->l2w[(i >> 5) * 33 + (i & 31)] = l2w[i];
    if (t < 32) { S->l3w[t] = l3w[t]; S->l1b[t] = l1b[t]; S->l2b[t] = l2b[t]; }
    if (t == 0) S->l3b = l3b[0];

    const float4* fb4 = (const float4*)ftb;
    const float4* acc4 = (const float4*)g_accraw;
    for (int i = t; i < 16 * 128; i += 256) {
        int r = i >> 7, k4 = i & 127;                 // k4<64: first half
        int row = row0 + r;
        bool sd = mode ? (((const unsigned char*)side)[row] != 0)
                       : (((const unsigned int*)side)[row] != 0u);
        int first = sd ? 0 : 1;                       // side -> white first
        int rs = row * 2 + ((k4 < 64) ? first : 1 - first);
        float4 v = acc4[(size_t)rs * 64 + (k4 & 63)];
        float4 fb = fb4[k4 & 63];
        v.x += fb.x; v.y += fb.y; v.z += fb.z; v.w += fb.w;
        S->x4[r * 128 + k4] = clamp4(v);
    }
    __syncthreads();

    const int r0 = wid * 2, r1 = r0 + 1;
    const float4* wr = S->w4 + lane * 129;
    const float4* xa = S->x4 + r0 * 128;
    const float4* xb = S->x4 + r1 * 128;
    float s0 = 0.f, s1 = 0.f;
#pragma unroll 4
    for (int k = 0; k < 128; k++) {
        float4 wv = wr[k], u = xa[k], v = xb[k];
        s0 += ((wv.x * u.x + wv.y * u.y) + (wv.z * u.z + wv.w * u.w));
        s1 += ((wv.x * v.x + wv.y * v.y) + (wv.z * v.z + wv.w * v.w));
    }
    S->o1[r0 * 33 + lane] = clamp01(s0 + S->l1b[lane]);
    S->o1[r1 * 33 + lane] = clamp01(s1 + S->l1b[lane]);
    __syncwarp();

    float s2a = 0.f, s2b = 0.f;
#pragma unroll
    for (int k = 0; k < 32; k++) {
        float w2 = S->l2w[lane * 33 + k];             // (lane+k)%32: conflict-free
        s2a += w2 * S->o1[r0 * 33 + k];               // broadcast
        s2b += w2 * S->o1[r1 * 33 + k];
    }
    float va = clamp01(s2a + S->l2b[lane]) * S->l3w[lane];
    float vb = clamp01(s2b + S->l2b[lane]) * S->l3w[lane];
#pragma unroll
    for (int off = 16; off; off >>= 1) {
        va += __shfl_xor_sync(FULL, va, off);
        vb += __shfl_xor_sync(FULL, vb, off);
    }
    if (lane == 0) {
        out[row0 + r0] = 1.f / (1.f + expf(-(va + S->l3b) * 1.5f));  // 300/200
        out[row0 + r1] = 1.f / (1.f + expf(-(vb + S->l3b) * 1.5f));
    }
}

extern "C" void kernel_launch(void* const* d_in, const int* in_sizes, int n_in,
                              void* d_out, int out_size) {
    const float* wf  = (const float*)d_in[0];
    const float* bf  = (const float*)d_in[1];
    const void*  side = d_in[2];
    const float* ftw = (const float*)d_in[3];
    const float* ftb = (const float*)d_in[4];
    const float* l1w = (const float*)d_in[5];
    const float* l1b = (const float*)d_in[6];
    const float* l2w = (const float*)d_in[7];
    const float* l2b = (const float*)d_in[8];
    const float* l3w = (const float*)d_in[9];
    const float* l3b = (const float*)d_in[10];
    float* out = (float*)d_out;

    cudaFuncSetAttribute(mlp_kernel, cudaFuncAttributeMaxDynamicSharedMemorySize,
                         (int)sizeof(SmemM));

    detect_side_mode<<<1, 32>>>((const unsigned int*)side);
    transpose_ft<<<dim3(N_IN / 32, H0 / 32), dim3(32, 8)>>>(ftw);
    scan_kernel<<<NB * 2, 256>>>(wf, bf);
    gather_kernel<<<NB * 2 / 8, 256>>>();
    mlp_kernel<<<NB / 16, 256, sizeof(SmemM)>>>(side, ftb, l1w, l1b, l2w, l2b,
                                                l3w, l3b, out);
}

// round 8
// speedup vs baseline: 2.7627x; 1.2628x over previous
#include <cuda_runtime.h>
#include <math.h>

#define N_IN 12288
#define H0 256
#define H1 32
#define H2 32
#define NB 8192
#define SEG_CAP 32        // per-warp-slice capacity (Binomial(1536,.0025): mean 3.8, z>14 safe)
#define FULL 0xffffffffu

// Transposed ft weights: column j = 256 contiguous floats (12.6 MB, L2-resident).
__device__ float g_ftT[N_IN * H0];
// Raw (unswapped, unclamped, no-bias) accumulators [row-side R][256] (16 MB).
__device__ float g_accraw[NB * 2 * H0];
// 0 = 32-bit words (int32/fp32; !=0 covers both), 1 = packed bytes.
__device__ int g_side_mode;

__global__ void detect_side_mode(const unsigned int* __restrict__ w) {
    int lane = threadIdx.x;
    bool bad = false;
#pragma unroll
    for (int i = 0; i < 8; i++) {
        unsigned int v = w[i * 32 + lane];
        bad |= (v != 0u && v != 1u && v != 0x3f800000u);
    }
    unsigned m = __ballot_sync(FULL, bad);
    if (lane == 0) g_side_mode = (m != 0u) ? 1 : 0;
}

__global__ void transpose_ft(const float* __restrict__ ftw) {
    __shared__ float tile[32][33];
    int j0 = blockIdx.x * 32, h0 = blockIdx.y * 32;
    int tx = threadIdx.x, ty = threadIdx.y;
#pragma unroll
    for (int r = 0; r < 32; r += 8)
        tile[ty + r][tx] = ftw[(size_t)(h0 + ty + r) * N_IN + j0 + tx];
    __syncthreads();
#pragma unroll
    for (int r = 0; r < 32; r += 8)
        g_ftT[(size_t)(j0 + ty + r) * H0 + h0 + tx] = tile[tx][ty + r];
}

__device__ __forceinline__ float clamp01(float x) { return fminf(fmaxf(x, 0.f), 1.f); }
__device__ __forceinline__ float4 clamp4(float4 a) {
    return make_float4(clamp01(a.x), clamp01(a.y), clamp01(a.z), clamp01(a.w));
}
__device__ __forceinline__ void add4(float4& a, float4 u) {
    a.x += u.x; a.y += u.y; a.z += u.z; a.w += u.w;
}

// ============================================================================
// FT (fused scan+gather): one CTA per row-side. DRAM streaming (__ldcs,
// evict-first: protects the L2-resident ft table) overlaps with other CTAs'
// L2 gathers. Front-batched 12x LDG.128 stash -> ballot/popc smem lists ->
// round-robin warp gather (warp-uniform broadcast indices, float4 columns)
// -> fixed-order 8-way reduce. Fully deterministic.
// ============================================================================
__global__ __launch_bounds__(256) void ft_kernel(
    const float* __restrict__ wf, const float* __restrict__ bf)
{
    __shared__ unsigned short lists[8][SEG_CAP];
    __shared__ int cnts[8];
    __shared__ float partial[8][H0];

    const int R = blockIdx.x;                       // row-side: row=R>>1, side=R&1
    const float* base = (R & 1) ? bf : wf;
    const uint4* rowp = (const uint4*)(base + (size_t)(R >> 1) * N_IN);
    const int t = threadIdx.x, lane = t & 31, wid = t >> 5;
    const unsigned lt = (1u << lane) - 1u;

    // ---- front-batched stream (MLP_p1 = 12), evict-first in L2 ----
    uint4 st[12];
#pragma unroll
    for (int i = 0; i < 12; i++) st[i] = __ldcs(rowp + i * 256 + t);

    // ---- ballot/popc compaction into per-warp smem segment ----
    int n = 0;
    unsigned short* seg = lists[wid];
#pragma unroll
    for (int i = 0; i < 12; i++) {
        uint4 v = st[i];
        bool f0 = v.x != 0u, f1 = v.y != 0u, f2 = v.z != 0u, f3 = v.w != 0u;
        unsigned b0 = __ballot_sync(FULL, f0);
        unsigned b1 = __ballot_sync(FULL, f1);
        unsigned b2 = __ballot_sync(FULL, f2);
        unsigned b3 = __ballot_sync(FULL, f3);
        if (b0 | b1 | b2 | b3) {                     // ~96% all-zero warp-wide
            int ib = (i * 256 + t) * 4;
            int c0 = __popc(b0), c01 = c0 + __popc(b1), c012 = c01 + __popc(b2);
            if (f0) { int q = n + __popc(b0 & lt);        if (q < SEG_CAP) seg[q] = (unsigned short)ib; }
            if (f1) { int q = n + c0 + __popc(b1 & lt);   if (q < SEG_CAP) seg[q] = (unsigned short)(ib + 1); }
            if (f2) { int q = n + c01 + __popc(b2 & lt);  if (q < SEG_CAP) seg[q] = (unsigned short)(ib + 2); }
            if (f3) { int q = n + c012 + __popc(b3 & lt); if (q < SEG_CAP) seg[q] = (unsigned short)(ib + 3); }
            n += c012 + __popc(b3);
        }
    }
    if (lane == 0) cnts[wid] = min(n, SEG_CAP);
    __syncthreads();

    // ---- gather: warp w takes global positions p ≡ w (mod 8) ----
    float4 a0 = make_float4(0, 0, 0, 0), a1 = a0;
    const float4* tab = (const float4*)g_ftT;
    {
        int gpos = 0;
#pragma unroll
        for (int s = 0; s < 8; s++) {
            int c = cnts[s];
            int p0 = gpos + ((wid - gpos) & 7);      // first p ≥ gpos with p%8==wid
            const unsigned short* sl = lists[s];
            for (int p = p0; p < gpos + c; p += 8) {
                int idx = sl[p - gpos];              // warp-uniform broadcast
                const float4* cp = tab + idx * 64 + lane * 2;
                float4 u0 = cp[0], u1 = cp[1];
                add4(a0, u0); add4(a1, u1);
            }
            gpos += c;
        }
    }
    ((float4*)partial[wid])[lane * 2]     = a0;
    ((float4*)partial[wid])[lane * 2 + 1] = a1;
    __syncthreads();

    // ---- fixed-order 8-way reduce; raw accumulator out ----
    float sum = partial[0][t];
#pragma unroll
    for (int w = 1; w < 8; w++) sum += partial[w][t];
    g_accraw[(size_t)R * H0 + t] = sum;
}

// ============================================================================
// MLP: 16 rows per CTA, 2 rows per warp. Lane o owns output o -> no shfl
// chains in l1/l2. ftb add, clamp, side-swap fused into x staging.
// ============================================================================
struct SmemM {
    float4 w4[32 * 129];     // l1w, stride 129 -> conflict-free LDS.128
    float4 x4[16 * 128];     // 16 rows x 512 inputs
    float o1[16 * 33];
    float l2w[32 * 33];
    float l3w[32], l1b[32], l2b[32];
    float l3b;
};

__global__ __launch_bounds__(256) void mlp_kernel(
    const void* __restrict__ side, const float* __restrict__ ftb,
    const float* __restrict__ l1w, const float* __restrict__ l1b,
    const float* __restrict__ l2w, const float* __restrict__ l2b,
    const float* __restrict__ l3w, const float* __restrict__ l3b,
    float* __restrict__ out)
{
    extern __shared__ unsigned char raw[];
    SmemM* S = (SmemM*)raw;
    const int t = threadIdx.x, lane = t & 31, wid = t >> 5;
    const int row0 = blockIdx.x * 16;
    const int mode = g_side_mode;

    for (int i = t; i < 32 * 128; i += 256) {
        int o = i >> 7, k4 = i & 127;
        S->w4[o * 129 + k4] = ((const float4*)l1w)[i];
    }
    for (int i = t; i < 32 * 32; i += 256)
        S->l2w[(i >> 5) * 33 + (i & 31)] = l2w[i];
    if (t < 32) { S->l3w[t] = l3w[t]; S->l1b[t] = l1b[t]; S->l2b[t] = l2b[t]; }
    if (t == 0) S->l3b = l3b[0];

    const float4* fb4 = (const float4*)ftb;
    const float4* acc4 = (const float4*)g_accraw;
    for (int i = t; i < 16 * 128; i += 256) {
        int r = i >> 7, k4 = i & 127;                 // k4<64: first half
        int row = row0 + r;
        bool sd = mode ? (((const unsigned char*)side)[row] != 0)
                       : (((const unsigned int*)side)[row] != 0u);
        int first = sd ? 0 : 1;                       // side -> white first
        int rs = row * 2 + ((k4 < 64) ? first : 1 - first);
        float4 v = acc4[(size_t)rs * 64 + (k4 & 63)];
        float4 fb = fb4[k4 & 63];
        v.x += fb.x; v.y += fb.y; v.z += fb.z; v.w += fb.w;
        S->x4[r * 128 + k4] = clamp4(v);
    }
    __syncthreads();

    const int r0 = wid * 2, r1 = r0 + 1;
    const float4* wr = S->w4 + lane * 129;
    const float4* xa = S->x4 + r0 * 128;
    const float4* xb = S->x4 + r1 * 128;
    float s0 = 0.f, s1 = 0.f;
#pragma unroll 4
    for (int k = 0; k < 128; k++) {
        float4 wv = wr[k], u = xa[k], v = xb[k];
        s0 += ((wv.x * u.x + wv.y * u.y) + (wv.z * u.z + wv.w * u.w));
        s1 += ((wv.x * v.x + wv.y * v.y) + (wv.z * v.z + wv.w * v.w));
    }
    S->o1[r0 * 33 + lane] = clamp01(s0 + S->l1b[lane]);
    S->o1[r1 * 33 + lane] = clamp01(s1 + S->l1b[lane]);
    __syncwarp();

    float s2a = 0.f, s2b = 0.f;
#pragma unroll
    for (int k = 0; k < 32; k++) {
        float w2 = S->l2w[lane * 33 + k];
        s2a += w2 * S->o1[r0 * 33 + k];
        s2b += w2 * S->o1[r1 * 33 + k];
    }
    float va = clamp01(s2a + S->l2b[lane]) * S->l3w[lane];
    float vb = clamp01(s2b + S->l2b[lane]) * S->l3w[lane];
#pragma unroll
    for (int off = 16; off; off >>= 1) {
        va += __shfl_xor_sync(FULL, va, off);
        vb += __shfl_xor_sync(FULL, vb, off);
    }
    if (lane == 0) {
        out[row0 + r0] = 1.f / (1.f + expf(-(va + S->l3b) * 1.5f));  // 300/200
        out[row0 + r1] = 1.f / (1.f + expf(-(vb + S->l3b) * 1.5f));
    }
}

extern "C" void kernel_launch(void* const* d_in, const int* in_sizes, int n_in,
                              void* d_out, int out_size) {
    const float* wf  = (const float*)d_in[0];
    const float* bf  = (const float*)d_in[1];
    const void*  side = d_in[2];
    const float* ftw = (const float*)d_in[3];
    const float* ftb = (const float*)d_in[4];
    const float* l1w = (const float*)d_in[5];
    const float* l1b = (const float*)d_in[6];
    const float* l2w = (const float*)d_in[7];
    const float* l2b = (const float*)d_in[8];
    const float* l3w = (const float*)d_in[9];
    const float* l3b = (const float*)d_in[10];
    float* out = (float*)d_out;

    cudaFuncSetAttribute(mlp_kernel, cudaFuncAttributeMaxDynamicSharedMemorySize,
                         (int)sizeof(SmemM));

    detect_side_mode<<<1, 32>>>((const unsigned int*)side);
    transpose_ft<<<dim3(N_IN / 32, H0 / 32), dim3(32, 8)>>>(ftw);
    ft_kernel<<<NB * 2, 256>>>(wf, bf);
    mlp_kernel<<<NB / 16, 256, sizeof(SmemM)>>>(side, ftb, l1w, l1b, l2w, l2b,
                                                l3w, l3b, out);
}